// round 4
// baseline (speedup 1.0000x reference)
#include <cuda_runtime.h>
#include <cuda_bf16.h>
#include <mma.h>
#include <math.h>
#include <cstdint>

using namespace nvcuda;

#define NTOT   131072
#define DIM    512
#define DATT   256
#define NHEAD  4
#define NCLS   53
#define BAGSZ  16
#define NBAGS  8192

#define TM   64          // rows per block (4 bags); grid 2048
#define KC   32          // K chunk
#define NCHUNK (DIM / KC)  // 16
#define A_LD 520         // bf16/row (512 + 8 pad)
#define B_LD 264         // bf16/row (256 + 8 pad)
#define H_LD 260         // f32/row

// smem layout (bytes)
#define OFF_A_HI 0                        // 64*520*2 = 66560
#define OFF_A_LO 66560
#define OFF_B    133120                   // 2 bufs x (hi 16896 + lo 16896) = 67584
#define BUF_SZ   33792
#define BUF_HALF 16896                    // 32 rows * 528 B
#define OFF_H    OFF_B                    // 64*260*4 = 66560 (fits in 67584)
#define OFF_W2   200704                   // 4096
#define OFF_SS   204800                   // 1024
#define OFF_WR   205824                   // 256
#define OFF_REPR 206080                   // 4*512*4 = 8192
#define OFF_WC   214272                   // 64*64*4 = 16384
#define SMEM_TOTAL 230656

// pre-packed W1: [chunk(16)][hi/lo][kk(32)][n(256)] bf16 = 512 KB
__device__ __align__(16) __nv_bfloat16 g_Wpk[NCHUNK * 2 * KC * DATT];

extern __shared__ char smem_raw[];

__device__ __forceinline__ uint32_t smem_u32(const void* p) {
    uint32_t a;
    asm("{ .reg .u64 t; cvta.to.shared.u64 t, %1; cvt.u32.u64 %0, t; }" : "=r"(a) : "l"(p));
    return a;
}
__device__ __forceinline__ void cp16(uint32_t dst, const void* src) {
    asm volatile("cp.async.ca.shared.global [%0], [%1], 16;" :: "r"(dst), "l"(src));
}
#define CP_COMMIT() asm volatile("cp.async.commit_group;" ::: "memory")
#define CP_WAIT1()  asm volatile("cp.async.wait_group 1;" ::: "memory")
#define CP_WAIT0()  asm volatile("cp.async.wait_group 0;" ::: "memory")

__device__ __forceinline__ void split_store4(float4 v, __nv_bfloat16* hi, __nv_bfloat16* lo)
{
    __nv_bfloat16 h0 = __float2bfloat16(v.x);
    __nv_bfloat16 h1 = __float2bfloat16(v.y);
    __nv_bfloat16 h2 = __float2bfloat16(v.z);
    __nv_bfloat16 h3 = __float2bfloat16(v.w);
    hi[0] = h0; hi[1] = h1; hi[2] = h2; hi[3] = h3;
    lo[0] = __float2bfloat16(v.x - __bfloat162float(h0));
    lo[1] = __float2bfloat16(v.y - __bfloat162float(h1));
    lo[2] = __float2bfloat16(v.z - __bfloat162float(h2));
    lo[3] = __float2bfloat16(v.w - __bfloat162float(h3));
}

// one-time: W1 (512x256 f32) -> chunk-major bf16 hi/lo image
__global__ void wsplit_kernel(const float* __restrict__ W1) {
    const int idx = blockIdx.x * 256 + threadIdx.x;  // k*256 + n
    const int k = idx >> 8, n = idx & 255;
    const float v = W1[idx];
    __nv_bfloat16 h = __float2bfloat16(v);
    __nv_bfloat16 l = __float2bfloat16(v - __bfloat162float(h));
    const int c = k >> 5, kk = k & 31;
    const size_t base = (size_t)c * (2 * KC * DATT) + (size_t)kk * DATT + n;
    g_Wpk[base] = h;
    g_Wpk[base + KC * DATT] = l;
}

__device__ __forceinline__ void issue_b_chunk(int c, int buf, uint32_t sbase, int tid) {
    // 2048 x 16B transfers: [half(2)][row(32)][seg(32)]
    #pragma unroll
    for (int it = 0; it < 8; it++) {
        const int q    = it * 256 + tid;
        const int half = q >> 10;
        const int row  = (q >> 5) & 31;
        const int seg  = q & 31;
        const __nv_bfloat16* src = g_Wpk + (size_t)c * (2 * KC * DATT)
                                 + (size_t)half * (KC * DATT) + row * DATT + seg * 8;
        const uint32_t dst = sbase + OFF_B + buf * BUF_SZ + half * BUF_HALF
                           + row * (B_LD * 2) + seg * 16;
        cp16(dst, src);
    }
    CP_COMMIT();
}

__global__ __launch_bounds__(256)
void mlssa_main(const float* __restrict__ x, const float* __restrict__ W2,
                const float* __restrict__ Wc, const float* __restrict__ bc,
                float* __restrict__ out)
{
    const int tid  = threadIdx.x;
    const int wid  = tid >> 5;
    const int lane = tid & 31;
    const int row0 = blockIdx.x * TM;
    const uint32_t sbase = smem_u32(smem_raw);

    __nv_bfloat16* A_hi = (__nv_bfloat16*)(smem_raw + OFF_A_HI);
    __nv_bfloat16* A_lo = (__nv_bfloat16*)(smem_raw + OFF_A_LO);
    float* hbuf = (float*)(smem_raw + OFF_H);
    float* w2s  = (float*)(smem_raw + OFF_W2);
    float* ss   = (float*)(smem_raw + OFF_SS);
    float* wr   = (float*)(smem_raw + OFF_WR);
    float* repr = (float*)(smem_raw + OFF_REPR);
    float* wcs  = (float*)(smem_raw + OFF_WC);

    // kick off first two B chunks (overlaps with A staging)
    issue_b_chunk(0, 0, sbase, tid);
    issue_b_chunk(1, 1, sbase, tid);

    // stage x tile 64x512 -> bf16 hi/lo split (resident for whole kernel)
    {
        const float4* xg = (const float4*)(x + (size_t)row0 * DIM);
        #pragma unroll 4
        for (int i = tid; i < (TM * DIM) / 4; i += 256) {
            float4 v = xg[i];
            const int r = i >> 7;           // DIM/4 = 128
            const int c = (i & 127) * 4;
            split_store4(v, &A_hi[r * A_LD + c], &A_lo[r * A_LD + c]);
        }
    }
    for (int i = tid; i < DATT * NHEAD; i += 256) w2s[i] = W2[i];
    ss[tid] = 0.0f;

    // warp tiling: 8 warps = 2(M) x 4(N), warp tile 32x64
    const int warp_m = wid >> 2;
    const int warp_n = wid & 3;

    wmma::fragment<wmma::accumulator, 16, 16, 16, float> acc[2][4];
    #pragma unroll
    for (int i = 0; i < 2; i++)
        #pragma unroll
        for (int j = 0; j < 4; j++) wmma::fill_fragment(acc[i][j], 0.0f);

    for (int c = 0; c < NCHUNK; c++) {
        const int buf = c & 1;
        if (c == NCHUNK - 1) { CP_WAIT0(); } else { CP_WAIT1(); }
        __syncthreads();

        const __nv_bfloat16* Bh = (const __nv_bfloat16*)(smem_raw + OFF_B + buf * BUF_SZ);
        const __nv_bfloat16* Bl = (const __nv_bfloat16*)(smem_raw + OFF_B + buf * BUF_SZ + BUF_HALF);

        #pragma unroll
        for (int ks = 0; ks < 2; ks++) {
            const int kg = c * KC + ks * 16;   // global k for A
            wmma::fragment<wmma::matrix_a, 16, 16, 16, __nv_bfloat16, wmma::row_major> a_hi[2], a_lo[2];
            wmma::fragment<wmma::matrix_b, 16, 16, 16, __nv_bfloat16, wmma::row_major> b_hi[4], b_lo[4];
            #pragma unroll
            for (int i = 0; i < 2; i++) {
                const size_t ao = (size_t)(warp_m * 32 + i * 16) * A_LD + kg;
                wmma::load_matrix_sync(a_hi[i], A_hi + ao, A_LD);
                wmma::load_matrix_sync(a_lo[i], A_lo + ao, A_LD);
            }
            #pragma unroll
            for (int j = 0; j < 4; j++) {
                const size_t bo = (size_t)(ks * 16) * B_LD + warp_n * 64 + j * 16;
                wmma::load_matrix_sync(b_hi[j], Bh + bo, B_LD);
                wmma::load_matrix_sync(b_lo[j], Bl + bo, B_LD);
            }
            #pragma unroll
            for (int i = 0; i < 2; i++)
                #pragma unroll
                for (int j = 0; j < 4; j++) {
                    wmma::mma_sync(acc[i][j], a_hi[i], b_hi[j], acc[i][j]);
                    wmma::mma_sync(acc[i][j], a_hi[i], b_lo[j], acc[i][j]);
                    wmma::mma_sync(acc[i][j], a_lo[i], b_hi[j], acc[i][j]);
                }
        }

        __syncthreads();               // all warps done reading this buf
        if (c + 2 < NCHUNK) issue_b_chunk(c + 2, buf, sbase, tid);
    }

    __syncthreads();                   // B buffers dead -> h overlay safe
    #pragma unroll
    for (int i = 0; i < 2; i++)
        #pragma unroll
        for (int j = 0; j < 4; j++)
            wmma::store_matrix_sync(
                hbuf + (size_t)(warp_m * 32 + i * 16) * H_LD + warp_n * 64 + j * 16,
                acc[i][j], H_LD, wmma::mem_row_major);
    __syncthreads();

    // scores: s[r][h] = sum_c tanh(h[r][c]) * W2[c][h]
    {
        const int r = tid & 63;
        const int q = tid >> 6;        // column quarter
        float sp0 = 0.f, sp1 = 0.f, sp2 = 0.f, sp3 = 0.f;
        const float* hr = hbuf + (size_t)r * H_LD + q * 64;
        #pragma unroll
        for (int jj = 0; jj < 16; jj++) {
            const float4 hv = *(const float4*)&hr[jj * 4];
            #pragma unroll
            for (int s = 0; s < 4; s++) {
                const float hvv = (s == 0) ? hv.x : (s == 1) ? hv.y : (s == 2) ? hv.z : hv.w;
                const float t = tanhf(hvv);
                const int cc = q * 64 + jj * 4 + s;
                const float4 wv = *(const float4*)&w2s[cc * 4];
                sp0 += t * wv.x; sp1 += t * wv.y; sp2 += t * wv.z; sp3 += t * wv.w;
            }
        }
        atomicAdd(&ss[r * 4 + 0], sp0);
        atomicAdd(&ss[r * 4 + 1], sp1);
        atomicAdd(&ss[r * 4 + 2], sp2);
        atomicAdd(&ss[r * 4 + 3], sp3);
    }
    __syncthreads();

    // per-bag softmax over 16 rows, mean over 4 heads
    if (tid < TM) {
        const int r = tid, b0 = r & ~15;
        float ws = 0.f;
        #pragma unroll
        for (int h = 0; h < NHEAD; h++) {
            float m = -1e30f;
            #pragma unroll
            for (int q = 0; q < BAGSZ; q++) m = fmaxf(m, ss[(b0 + q) * 4 + h]);
            float den = 0.f;
            #pragma unroll
            for (int q = 0; q < BAGSZ; q++) den += expf(ss[(b0 + q) * 4 + h] - m);
            ws += expf(ss[r * 4 + h] - m) / den;
        }
        wr[r] = ws * 0.25f;
    }
    __syncthreads();

    // pooling: thread owns 2 dims across all 4 bags; reconstruct x = hi + lo
    {
        const int d0 = tid * 2;
        #pragma unroll
        for (int b = 0; b < TM / BAGSZ; b++) {
            float s0 = 0.f, s1 = 0.f;
            #pragma unroll
            for (int q = 0; q < BAGSZ; q++) {
                const int rr = b * BAGSZ + q;
                const float w = wr[rr];
                s0 += w * (__bfloat162float(A_hi[rr * A_LD + d0]) +
                           __bfloat162float(A_lo[rr * A_LD + d0]));
                s1 += w * (__bfloat162float(A_hi[rr * A_LD + d0 + 1]) +
                           __bfloat162float(A_lo[rr * A_LD + d0 + 1]));
            }
            repr[b * DIM + d0]     = s0;
            repr[b * DIM + d0 + 1] = s1;
        }
    }
    __syncthreads();

    // fused classifier: logits[bag] = repr[bag] @ Wc + bc
    {
        const int bag = tid >> 6;      // 0..3
        const int cls = tid & 63;      // 0..63 (valid < 53)
        float acc0 = 0.f;
        for (int k0 = 0; k0 < DIM; k0 += 64) {
            __syncthreads();
            for (int i = tid; i < 64 * 64; i += 256) {
                const int kk = i >> 6, cc = i & 63;
                wcs[i] = (cc < NCLS) ? Wc[(size_t)(k0 + kk) * NCLS + cc] : 0.f;
            }
            __syncthreads();
            #pragma unroll 8
            for (int kk = 0; kk < 64; kk++)
                acc0 += repr[bag * DIM + k0 + kk] * wcs[kk * 64 + cls];
        }
        if (cls < NCLS) {
            const int bag_g = blockIdx.x * (TM / BAGSZ) + bag;
            out[(size_t)bag_g * NCLS + cls] = acc0 + bc[cls];
        }
    }
}

extern "C" void kernel_launch(void* const* d_in, const int* in_sizes, int n_in,
                              void* d_out, int out_size)
{
    const float* x  = (const float*)d_in[0];
    const float* W1 = (const float*)d_in[1];
    const float* W2 = (const float*)d_in[2];
    const float* Wc = (const float*)d_in[3];
    const float* bc = (const float*)d_in[4];
    float* out = (float*)d_out;

    cudaFuncSetAttribute(mlssa_main,
                         cudaFuncAttributeMaxDynamicSharedMemorySize, SMEM_TOTAL);

    wsplit_kernel<<<512, 256>>>(W1);
    mlssa_main<<<NTOT / TM, 256, SMEM_TOTAL>>>(x, W2, Wc, bc, out);
}

// round 5
// speedup vs baseline: 1.1835x; 1.1835x over previous
#include <cuda_runtime.h>
#include <cuda_bf16.h>
#include <mma.h>
#include <math.h>
#include <cstdint>

using namespace nvcuda;

#define NTOT   131072
#define DIM    512
#define DATT   256
#define NHEAD  4
#define NCLS   53
#define BAGSZ  16
#define NBAGS  8192

#define TM   64            // rows per block (4 bags); grid 2048
#define KC   32            // K chunk
#define NCHUNK (DIM / KC)  // 16
#define A_LD 40            // bf16/row in A chunk (32 + 8 pad) -> 80 B rows
#define B_LD 264           // bf16/row in B chunk (256 + 8 pad)
#define H_LD 260

// smem layout (bytes)
#define A_HALF   5120              // 64 rows * 80 B
#define A_BUFSZ  10240             // hi + lo
#define B_HALF   16896             // 32 rows * 528 B
#define B_BUFSZ  33792
#define OFF_A0   0
#define OFF_A1   10240
#define OFF_B0   20480
#define OFF_B1   54272
#define OFF_H    0                 // overlays pipeline after GEMM (66560 <= 88064)
#define OFF_WC   66560             // 16384, overlays B buf tail during classifier
#define OFF_W2   88064             // 4096
#define OFF_SS   92160             // 1024
#define OFF_WR   93184             // 256
#define OFF_REPR 93440             // 8192
#define SMEM_TOTAL 101632          // ~99.25 KB -> 2 CTAs/SM

// pre-split weights / activations (device globals per allocation rules)
__device__ __align__(16) __nv_bfloat16 g_Wpk[NCHUNK * 2 * KC * DATT];      // 512 KB
__device__ __align__(16) __nv_bfloat16 g_x_hi[(size_t)NTOT * DIM];        // 128 MB
__device__ __align__(16) __nv_bfloat16 g_x_lo[(size_t)NTOT * DIM];        // 128 MB

extern __shared__ char smem_raw[];

__device__ __forceinline__ uint32_t smem_u32(const void* p) {
    uint32_t a;
    asm("{ .reg .u64 t; cvta.to.shared.u64 t, %1; cvt.u32.u64 %0, t; }" : "=r"(a) : "l"(p));
    return a;
}
__device__ __forceinline__ void cp16(uint32_t dst, const void* src) {
    asm volatile("cp.async.ca.shared.global [%0], [%1], 16;" :: "r"(dst), "l"(src));
}
#define CP_COMMIT() asm volatile("cp.async.commit_group;" ::: "memory")
#define CP_WAIT1()  asm volatile("cp.async.wait_group 1;" ::: "memory")
#define CP_WAIT0()  asm volatile("cp.async.wait_group 0;" ::: "memory")

// ---- one-time: W1 (512x256 f32) -> chunk-major bf16 hi/lo image ----
__global__ void wsplit_kernel(const float* __restrict__ W1) {
    const int idx = blockIdx.x * 256 + threadIdx.x;   // k*256 + n
    const int k = idx >> 8, n = idx & 255;
    const float v = W1[idx];
    __nv_bfloat16 h = __float2bfloat16(v);
    __nv_bfloat16 l = __float2bfloat16(v - __bfloat162float(h));
    const int c = k >> 5, kk = k & 31;
    const size_t base = (size_t)c * (2 * KC * DATT) + (size_t)kk * DATT + n;
    g_Wpk[base] = h;
    g_Wpk[base + KC * DATT] = l;
}

// ---- one-time: x (f32) -> bf16 hi/lo arrays ----
__global__ __launch_bounds__(256) void xsplit_kernel(const float* __restrict__ x) {
    const size_t i4 = (size_t)blockIdx.x * 256 + threadIdx.x;   // float4 index
    const float4 v = ((const float4*)x)[i4];
    __nv_bfloat16 h0 = __float2bfloat16(v.x), h1 = __float2bfloat16(v.y);
    __nv_bfloat16 h2 = __float2bfloat16(v.z), h3 = __float2bfloat16(v.w);
    __nv_bfloat16 l0 = __float2bfloat16(v.x - __bfloat162float(h0));
    __nv_bfloat16 l1 = __float2bfloat16(v.y - __bfloat162float(h1));
    __nv_bfloat16 l2 = __float2bfloat16(v.z - __bfloat162float(h2));
    __nv_bfloat16 l3 = __float2bfloat16(v.w - __bfloat162float(h3));
    uint32_t hA = (uint32_t)__bfloat16_as_ushort(h0) | ((uint32_t)__bfloat16_as_ushort(h1) << 16);
    uint32_t hB = (uint32_t)__bfloat16_as_ushort(h2) | ((uint32_t)__bfloat16_as_ushort(h3) << 16);
    uint32_t lA = (uint32_t)__bfloat16_as_ushort(l0) | ((uint32_t)__bfloat16_as_ushort(l1) << 16);
    uint32_t lB = (uint32_t)__bfloat16_as_ushort(l2) | ((uint32_t)__bfloat16_as_ushort(l3) << 16);
    ((uint2*)g_x_hi)[i4] = make_uint2(hA, hB);
    ((uint2*)g_x_lo)[i4] = make_uint2(lA, lB);
}

__device__ __forceinline__ void issue_chunk(int c, int buf, uint32_t sbase, int tid, int row0) {
    const int k0 = c * KC;
    // B: 2048 x 16B, [half(2)][row(32)][seg(32)]
    const uint32_t bdst0 = sbase + (buf ? OFF_B1 : OFF_B0);
    #pragma unroll
    for (int it = 0; it < 8; it++) {
        const int q = it * 256 + tid;
        const int half = q >> 10, row = (q >> 5) & 31, seg = q & 31;
        const __nv_bfloat16* src = g_Wpk + (size_t)c * (2 * KC * DATT)
                                 + (size_t)half * (KC * DATT) + row * DATT + seg * 8;
        cp16(bdst0 + half * B_HALF + row * (B_LD * 2) + seg * 16, src);
    }
    // A: 512 x 16B, [half(2)][row(64)][seg(4)]
    const uint32_t adst0 = sbase + (buf ? OFF_A1 : OFF_A0);
    #pragma unroll
    for (int it = 0; it < 2; it++) {
        const int q = it * 256 + tid;
        const int half = q >> 8, row = (q >> 2) & 63, seg = q & 3;
        const __nv_bfloat16* base = half ? g_x_lo : g_x_hi;
        const __nv_bfloat16* src = base + (size_t)(row0 + row) * DIM + k0 + seg * 8;
        cp16(adst0 + half * A_HALF + row * (A_LD * 2) + seg * 16, src);
    }
    CP_COMMIT();
}

__global__ __launch_bounds__(256, 2)
void mlssa_main(const float* __restrict__ W2, const float* __restrict__ Wc,
                const float* __restrict__ bc, float* __restrict__ out)
{
    const int tid  = threadIdx.x;
    const int wid  = tid >> 5;
    const int lane = tid & 31;
    const int row0 = blockIdx.x * TM;
    const uint32_t sbase = smem_u32(smem_raw);

    float* hbuf = (float*)(smem_raw + OFF_H);
    float* wcs  = (float*)(smem_raw + OFF_WC);
    float* w2s  = (float*)(smem_raw + OFF_W2);
    float* ss   = (float*)(smem_raw + OFF_SS);
    float* wr   = (float*)(smem_raw + OFF_WR);
    float* repr = (float*)(smem_raw + OFF_REPR);

    issue_chunk(0, 0, sbase, tid, row0);
    issue_chunk(1, 1, sbase, tid, row0);

    for (int i = tid; i < DATT * NHEAD; i += 256) w2s[i] = W2[i];
    ss[tid] = 0.0f;

    const int warp_m = wid >> 2;   // 2(M) x 4(N) warp grid, warp tile 32x64
    const int warp_n = wid & 3;

    wmma::fragment<wmma::accumulator, 16, 16, 16, float> acc[2][4];
    #pragma unroll
    for (int i = 0; i < 2; i++)
        #pragma unroll
        for (int j = 0; j < 4; j++) wmma::fill_fragment(acc[i][j], 0.0f);

    for (int c = 0; c < NCHUNK; c++) {
        const int buf = c & 1;
        if (c == NCHUNK - 1) { CP_WAIT0(); } else { CP_WAIT1(); }
        __syncthreads();

        const __nv_bfloat16* Ah = (const __nv_bfloat16*)(smem_raw + (buf ? OFF_A1 : OFF_A0));
        const __nv_bfloat16* Al = (const __nv_bfloat16*)((const char*)Ah + A_HALF);
        const __nv_bfloat16* Bh = (const __nv_bfloat16*)(smem_raw + (buf ? OFF_B1 : OFF_B0));
        const __nv_bfloat16* Bl = (const __nv_bfloat16*)((const char*)Bh + B_HALF);

        #pragma unroll
        for (int ks = 0; ks < 2; ks++) {
            wmma::fragment<wmma::matrix_a, 16, 16, 16, __nv_bfloat16, wmma::row_major> a_hi[2], a_lo[2];
            wmma::fragment<wmma::matrix_b, 16, 16, 16, __nv_bfloat16, wmma::row_major> b_hi[4], b_lo[4];
            #pragma unroll
            for (int i = 0; i < 2; i++) {
                const size_t ao = (size_t)(warp_m * 32 + i * 16) * A_LD + ks * 16;
                wmma::load_matrix_sync(a_hi[i], Ah + ao, A_LD);
                wmma::load_matrix_sync(a_lo[i], Al + ao, A_LD);
            }
            #pragma unroll
            for (int j = 0; j < 4; j++) {
                const size_t bo = (size_t)(ks * 16) * B_LD + warp_n * 64 + j * 16;
                wmma::load_matrix_sync(b_hi[j], Bh + bo, B_LD);
                wmma::load_matrix_sync(b_lo[j], Bl + bo, B_LD);
            }
            #pragma unroll
            for (int i = 0; i < 2; i++)
                #pragma unroll
                for (int j = 0; j < 4; j++) {
                    wmma::mma_sync(acc[i][j], a_hi[i], b_hi[j], acc[i][j]);
                    wmma::mma_sync(acc[i][j], a_hi[i], b_lo[j], acc[i][j]);
                    wmma::mma_sync(acc[i][j], a_lo[i], b_hi[j], acc[i][j]);
                }
        }

        __syncthreads();
        if (c + 2 < NCHUNK) issue_chunk(c + 2, buf, sbase, tid, row0);
    }

    __syncthreads();   // pipeline dead -> h overlay
    #pragma unroll
    for (int i = 0; i < 2; i++)
        #pragma unroll
        for (int j = 0; j < 4; j++)
            wmma::store_matrix_sync(
                hbuf + (size_t)(warp_m * 32 + i * 16) * H_LD + warp_n * 64 + j * 16,
                acc[i][j], H_LD, wmma::mem_row_major);
    __syncthreads();

    // scores: s[r][h] = sum_c tanh(h[r][c]) * W2[c][h]
    {
        const int r = tid & 63;
        const int q = tid >> 6;
        float sp0 = 0.f, sp1 = 0.f, sp2 = 0.f, sp3 = 0.f;
        const float* hr = hbuf + (size_t)r * H_LD + q * 64;
        #pragma unroll
        for (int jj = 0; jj < 16; jj++) {
            const float4 hv = *(const float4*)&hr[jj * 4];
            #pragma unroll
            for (int s = 0; s < 4; s++) {
                const float hvv = (s == 0) ? hv.x : (s == 1) ? hv.y : (s == 2) ? hv.z : hv.w;
                const float t = tanhf(hvv);
                const float4 wv = *(const float4*)&w2s[(q * 64 + jj * 4 + s) * 4];
                sp0 += t * wv.x; sp1 += t * wv.y; sp2 += t * wv.z; sp3 += t * wv.w;
            }
        }
        atomicAdd(&ss[r * 4 + 0], sp0);
        atomicAdd(&ss[r * 4 + 1], sp1);
        atomicAdd(&ss[r * 4 + 2], sp2);
        atomicAdd(&ss[r * 4 + 3], sp3);
    }
    __syncthreads();

    // per-bag softmax over 16 rows, mean over 4 heads
    if (tid < TM) {
        const int r = tid, b0 = r & ~15;
        float ws = 0.f;
        #pragma unroll
        for (int h = 0; h < NHEAD; h++) {
            float m = -1e30f;
            #pragma unroll
            for (int q = 0; q < BAGSZ; q++) m = fmaxf(m, ss[(b0 + q) * 4 + h]);
            float den = 0.f;
            #pragma unroll
            for (int q = 0; q < BAGSZ; q++) den += expf(ss[(b0 + q) * 4 + h] - m);
            ws += expf(ss[r * 4 + h] - m) / den;
        }
        wr[r] = ws * 0.25f;
    }
    __syncthreads();

    // pooling: thread owns 2 dims; reconstruct x = hi + lo from global (L2-hot)
    {
        const int d0 = tid * 2;
        #pragma unroll
        for (int b = 0; b < TM / BAGSZ; b++) {
            float s0 = 0.f, s1 = 0.f;
            #pragma unroll 4
            for (int q = 0; q < BAGSZ; q++) {
                const int rr = b * BAGSZ + q;
                const float w = wr[rr];
                const size_t off = (size_t)(row0 + rr) * DIM + d0;
                const uint32_t hv = *(const uint32_t*)&g_x_hi[off];
                const uint32_t lv = *(const uint32_t*)&g_x_lo[off];
                const float v0 = __bfloat162float(__ushort_as_bfloat16((unsigned short)(hv & 0xFFFF)))
                               + __bfloat162float(__ushort_as_bfloat16((unsigned short)(lv & 0xFFFF)));
                const float v1 = __bfloat162float(__ushort_as_bfloat16((unsigned short)(hv >> 16)))
                               + __bfloat162float(__ushort_as_bfloat16((unsigned short)(lv >> 16)));
                s0 += w * v0;
                s1 += w * v1;
            }
            repr[b * DIM + d0]     = s0;
            repr[b * DIM + d0 + 1] = s1;
        }
    }
    __syncthreads();

    // fused classifier
    {
        const int bag = tid >> 6;
        const int cls = tid & 63;
        float acc0 = 0.f;
        for (int k0 = 0; k0 < DIM; k0 += 64) {
            __syncthreads();
            for (int i = tid; i < 64 * 64; i += 256) {
                const int kk = i >> 6, cc = i & 63;
                wcs[i] = (cc < NCLS) ? Wc[(size_t)(k0 + kk) * NCLS + cc] : 0.f;
            }
            __syncthreads();
            #pragma unroll 8
            for (int kk = 0; kk < 64; kk++)
                acc0 += repr[bag * DIM + k0 + kk] * wcs[kk * 64 + cls];
        }
        if (cls < NCLS) {
            const int bag_g = blockIdx.x * (TM / BAGSZ) + bag;
            out[(size_t)bag_g * NCLS + cls] = acc0 + bc[cls];
        }
    }
}

extern "C" void kernel_launch(void* const* d_in, const int* in_sizes, int n_in,
                              void* d_out, int out_size)
{
    const float* x  = (const float*)d_in[0];
    const float* W1 = (const float*)d_in[1];
    const float* W2 = (const float*)d_in[2];
    const float* Wc = (const float*)d_in[3];
    const float* bc = (const float*)d_in[4];
    float* out = (float*)d_out;

    cudaFuncSetAttribute(mlssa_main,
                         cudaFuncAttributeMaxDynamicSharedMemorySize, SMEM_TOTAL);

    wsplit_kernel<<<512, 256>>>(W1);
    xsplit_kernel<<<(NTOT * DIM / 4) / 256, 256>>>(x);
    mlssa_main<<<NTOT / TM, 256, SMEM_TOTAL>>>(W2, Wc, bc, out);
}

// round 6
// speedup vs baseline: 2.1263x; 1.7966x over previous
#include <cuda_runtime.h>
#include <cuda_fp16.h>
#include <mma.h>
#include <math.h>
#include <cstdint>

using namespace nvcuda;

#define NTOT   131072
#define DIM    512
#define DATT   256
#define NHEAD  4
#define NCLS   53
#define BAGSZ  16
#define NBAGS  8192

#define TM     64            // rows per block (4 bags); grid 2048
#define KC     32            // K chunk
#define NCHUNK (DIM / KC)    // 16
#define NSTAGE 3
#define A_LD   40            // fp16/row (32 + 8 pad) -> 80 B rows
#define B_LD   264           // fp16/row (256 + 8 pad) -> 528 B rows
#define H_LD   260

// stage layout (bytes): A_hi 64*80=5120 | A_lo 5120 | B 32*528=16896
#define STAGE_SZ 27136
#define A_HI_OFF 0
#define A_LO_OFF 5120
#define B_OFF    10240
#define PIPE_SZ  (NSTAGE * STAGE_SZ)      // 81408

// overlays after GEMM: hbuf (66560) and later wcs (16384) live inside PIPE_SZ
#define OFF_W2   PIPE_SZ                  // 4096
#define OFF_SS   (OFF_W2 + 4096)          // 1024
#define OFF_WR   (OFF_SS + 1024)          // 256
#define OFF_REPR (OFF_WR + 256)           // 8192
#define SMEM_TOTAL (OFF_REPR + 8192)      // 94976 -> 2 CTAs/SM

// pre-converted W1 (fp16), chunk-major: [chunk(16)][kk(32)][n(256)]
__device__ __align__(16) __half g_Wpk[NCHUNK * KC * DATT];

extern __shared__ char smem_raw[];

__device__ __forceinline__ uint32_t smem_u32(const void* p) {
    uint32_t a;
    asm("{ .reg .u64 t; cvta.to.shared.u64 t, %1; cvt.u32.u64 %0, t; }" : "=r"(a) : "l"(p));
    return a;
}
__device__ __forceinline__ void cp16(uint32_t dst, const void* src) {
    asm volatile("cp.async.ca.shared.global [%0], [%1], 16;" :: "r"(dst), "l"(src));
}
#define CP_COMMIT() asm volatile("cp.async.commit_group;" ::: "memory")
#define CP_WAIT1()  asm volatile("cp.async.wait_group 1;" ::: "memory")
#define CP_WAIT0()  asm volatile("cp.async.wait_group 0;" ::: "memory")

// one-time: W1 (512x256 f32) -> chunk-major fp16 image
__global__ void wsplit_kernel(const float* __restrict__ W1) {
    const int idx = blockIdx.x * 256 + threadIdx.x;   // k*256 + n
    g_Wpk[idx] = __float2half(W1[idx]);               // chunk-major == k-major here
}

__device__ __forceinline__ void issue_b(int c, uint32_t sbase, int tid) {
    const uint32_t dst0 = sbase + (c % NSTAGE) * STAGE_SZ + B_OFF;
    const __half* src0 = g_Wpk + (size_t)c * (KC * DATT);
    #pragma unroll
    for (int it = 0; it < 4; it++) {
        const int q = it * 256 + tid;                  // 1024 x 16B
        const int row = q >> 5, seg = q & 31;
        cp16(dst0 + row * (B_LD * 2) + seg * 16, src0 + row * DATT + seg * 8);
    }
    CP_COMMIT();
}

// A chunk: each thread owns 8 consecutive floats of one row
__device__ __forceinline__ void ld_a(const float* __restrict__ x, int row0,
                                     int c, int tid, float4& v0, float4& v1) {
    const int row = tid >> 2, cg = tid & 3;
    const float* src = x + (size_t)(row0 + row) * DIM + c * KC + cg * 8;
    v0 = *(const float4*)src;
    v1 = *(const float4*)(src + 4);
}
__device__ __forceinline__ void st_a(int c, uint32_t sbase, int tid,
                                     float4 v0, float4 v1) {
    const int row = tid >> 2, cg = tid & 3;
    const uint32_t base = sbase + (c % NSTAGE) * STAGE_SZ + row * 80 + cg * 16;
    __half h0 = __float2half(v0.x), h1 = __float2half(v0.y);
    __half h2 = __float2half(v0.z), h3 = __float2half(v0.w);
    __half h4 = __float2half(v1.x), h5 = __float2half(v1.y);
    __half h6 = __float2half(v1.z), h7 = __float2half(v1.w);
    uint4 hi = make_uint4(
        (uint32_t)__half_as_ushort(h0) | ((uint32_t)__half_as_ushort(h1) << 16),
        (uint32_t)__half_as_ushort(h2) | ((uint32_t)__half_as_ushort(h3) << 16),
        (uint32_t)__half_as_ushort(h4) | ((uint32_t)__half_as_ushort(h5) << 16),
        (uint32_t)__half_as_ushort(h6) | ((uint32_t)__half_as_ushort(h7) << 16));
    __half l0 = __float2half(v0.x - __half2float(h0));
    __half l1 = __float2half(v0.y - __half2float(h1));
    __half l2 = __float2half(v0.z - __half2float(h2));
    __half l3 = __float2half(v0.w - __half2float(h3));
    __half l4 = __float2half(v1.x - __half2float(h4));
    __half l5 = __float2half(v1.y - __half2float(h5));
    __half l6 = __float2half(v1.z - __half2float(h6));
    __half l7 = __float2half(v1.w - __half2float(h7));
    uint4 lo = make_uint4(
        (uint32_t)__half_as_ushort(l0) | ((uint32_t)__half_as_ushort(l1) << 16),
        (uint32_t)__half_as_ushort(l2) | ((uint32_t)__half_as_ushort(l3) << 16),
        (uint32_t)__half_as_ushort(l4) | ((uint32_t)__half_as_ushort(l5) << 16),
        (uint32_t)__half_as_ushort(l6) | ((uint32_t)__half_as_ushort(l7) << 16));
    asm volatile("st.shared.v4.b32 [%0], {%1,%2,%3,%4};" ::
        "r"(base + A_HI_OFF), "r"(hi.x), "r"(hi.y), "r"(hi.z), "r"(hi.w));
    asm volatile("st.shared.v4.b32 [%0], {%1,%2,%3,%4};" ::
        "r"(base + A_LO_OFF), "r"(lo.x), "r"(lo.y), "r"(lo.z), "r"(lo.w));
}

__global__ __launch_bounds__(256, 2)
void mlssa_main(const float* __restrict__ x, const float* __restrict__ W2,
                const float* __restrict__ Wc, const float* __restrict__ bc,
                float* __restrict__ out)
{
    const int tid  = threadIdx.x;
    const int wid  = tid >> 5;
    const int row0 = blockIdx.x * TM;
    const uint32_t sbase = smem_u32(smem_raw);

    float* hbuf = (float*)(smem_raw);             // overlays pipeline post-GEMM
    float* wcs  = (float*)(smem_raw);             // overlays hbuf post-scores
    float* w2s  = (float*)(smem_raw + OFF_W2);
    float* ss   = (float*)(smem_raw + OFF_SS);
    float* wr   = (float*)(smem_raw + OFF_WR);
    float* repr = (float*)(smem_raw + OFF_REPR);

    // prologue: chunks 0,1 staged; prefetch chunk 2 into regs
    issue_b(0, sbase, tid);
    issue_b(1, sbase, tid);
    {
        float4 a0, a1;
        ld_a(x, row0, 0, tid, a0, a1); st_a(0, sbase, tid, a0, a1);
        ld_a(x, row0, 1, tid, a0, a1); st_a(1, sbase, tid, a0, a1);
    }
    float4 rA0, rA1;
    ld_a(x, row0, 2, tid, rA0, rA1);

    for (int i = tid; i < DATT * NHEAD; i += 256) w2s[i] = W2[i];
    ss[tid] = 0.0f;

    const int warp_m = wid >> 2;   // 2(M) x 4(N), warp tile 32x64
    const int warp_n = wid & 3;

    wmma::fragment<wmma::accumulator, 16, 16, 16, float> acc[2][4];
    #pragma unroll
    for (int i = 0; i < 2; i++)
        #pragma unroll
        for (int j = 0; j < 4; j++) wmma::fill_fragment(acc[i][j], 0.0f);

    for (int c = 0; c < NCHUNK; c++) {
        if (c == NCHUNK - 1) { CP_WAIT0(); } else { CP_WAIT1(); }
        __syncthreads();   // chunk c visible everywhere; stage (c+2)%3 dead

        if (c + 2 < NCHUNK) {
            st_a(c + 2, sbase, tid, rA0, rA1);
            issue_b(c + 2, sbase, tid);
            if (c + 3 < NCHUNK) ld_a(x, row0, c + 3, tid, rA0, rA1);
        }

        const char* stg = smem_raw + (c % NSTAGE) * STAGE_SZ;
        const __half* Ah = (const __half*)(stg + A_HI_OFF);
        const __half* Al = (const __half*)(stg + A_LO_OFF);
        const __half* Bp = (const __half*)(stg + B_OFF);

        #pragma unroll
        for (int ks = 0; ks < 2; ks++) {
            wmma::fragment<wmma::matrix_a, 16, 16, 16, __half, wmma::row_major> ah[2], al[2];
            wmma::fragment<wmma::matrix_b, 16, 16, 16, __half, wmma::row_major> bf[4];
            #pragma unroll
            for (int i = 0; i < 2; i++) {
                const size_t ao = (size_t)(warp_m * 32 + i * 16) * A_LD + ks * 16;
                wmma::load_matrix_sync(ah[i], Ah + ao, A_LD);
                wmma::load_matrix_sync(al[i], Al + ao, A_LD);
            }
            #pragma unroll
            for (int j = 0; j < 4; j++)
                wmma::load_matrix_sync(bf[j],
                    Bp + (size_t)(ks * 16) * B_LD + warp_n * 64 + j * 16, B_LD);
            #pragma unroll
            for (int i = 0; i < 2; i++)
                #pragma unroll
                for (int j = 0; j < 4; j++) {
                    wmma::mma_sync(acc[i][j], ah[i], bf[j], acc[i][j]);
                    wmma::mma_sync(acc[i][j], al[i], bf[j], acc[i][j]);
                }
        }
    }

    __syncthreads();   // pipeline dead -> h overlay safe
    #pragma unroll
    for (int i = 0; i < 2; i++)
        #pragma unroll
        for (int j = 0; j < 4; j++)
            wmma::store_matrix_sync(
                hbuf + (size_t)(warp_m * 32 + i * 16) * H_LD + warp_n * 64 + j * 16,
                acc[i][j], H_LD, wmma::mem_row_major);
    __syncthreads();

    // scores: s[r][h] = sum_c tanh(h[r][c]) * W2[c][h]
    {
        const int r = tid & 63;
        const int q = tid >> 6;
        float sp0 = 0.f, sp1 = 0.f, sp2 = 0.f, sp3 = 0.f;
        const float* hr = hbuf + (size_t)r * H_LD + q * 64;
        #pragma unroll
        for (int jj = 0; jj < 16; jj++) {
            const float4 hv = *(const float4*)&hr[jj * 4];
            #pragma unroll
            for (int s = 0; s < 4; s++) {
                const float hvv = (s == 0) ? hv.x : (s == 1) ? hv.y : (s == 2) ? hv.z : hv.w;
                const float t = tanhf(hvv);
                const float4 wv = *(const float4*)&w2s[(q * 64 + jj * 4 + s) * 4];
                sp0 += t * wv.x; sp1 += t * wv.y; sp2 += t * wv.z; sp3 += t * wv.w;
            }
        }
        atomicAdd(&ss[r * 4 + 0], sp0);
        atomicAdd(&ss[r * 4 + 1], sp1);
        atomicAdd(&ss[r * 4 + 2], sp2);
        atomicAdd(&ss[r * 4 + 3], sp3);
    }
    __syncthreads();

    // per-bag softmax over 16 rows, mean over 4 heads
    if (tid < TM) {
        const int r = tid, b0 = r & ~15;
        float ws = 0.f;
        #pragma unroll
        for (int h = 0; h < NHEAD; h++) {
            float m = -1e30f;
            #pragma unroll
            for (int q = 0; q < BAGSZ; q++) m = fmaxf(m, ss[(b0 + q) * 4 + h]);
            float den = 0.f;
            #pragma unroll
            for (int q = 0; q < BAGSZ; q++) den += expf(ss[(b0 + q) * 4 + h] - m);
            ws += expf(ss[r * 4 + h] - m) / den;
        }
        wr[r] = ws * 0.25f;
    }
    __syncthreads();

    // pooling: thread owns 2 dims across 4 bags; exact fp32 x from global (L2-hot)
    {
        const int d0 = tid * 2;
        #pragma unroll
        for (int b = 0; b < TM / BAGSZ; b++) {
            float s0 = 0.f, s1 = 0.f;
            #pragma unroll 4
            for (int q = 0; q < BAGSZ; q++) {
                const int rr = b * BAGSZ + q;
                const float w = wr[rr];
                const float2 v = *(const float2*)(x + (size_t)(row0 + rr) * DIM + d0);
                s0 += w * v.x;
                s1 += w * v.y;
            }
            repr[b * DIM + d0]     = s0;
            repr[b * DIM + d0 + 1] = s1;
        }
    }
    __syncthreads();

    // fused classifier: logits[bag] = repr[bag] @ Wc + bc
    {
        const int bag = tid >> 6;
        const int cls = tid & 63;
        float acc0 = 0.f;
        for (int k0 = 0; k0 < DIM; k0 += 64) {
            __syncthreads();
            for (int i = tid; i < 64 * 64; i += 256) {
                const int kk = i >> 6, cc = i & 63;
                wcs[i] = (cc < NCLS) ? Wc[(size_t)(k0 + kk) * NCLS + cc] : 0.f;
            }
            __syncthreads();
            #pragma unroll 8
            for (int kk = 0; kk < 64; kk++)
                acc0 += repr[bag * DIM + k0 + kk] * wcs[kk * 64 + cls];
        }
        if (cls < NCLS) {
            const int bag_g = blockIdx.x * (TM / BAGSZ) + bag;
            out[(size_t)bag_g * NCLS + cls] = acc0 + bc[cls];
        }
    }
}

extern "C" void kernel_launch(void* const* d_in, const int* in_sizes, int n_in,
                              void* d_out, int out_size)
{
    const float* x  = (const float*)d_in[0];
    const float* W1 = (const float*)d_in[1];
    const float* W2 = (const float*)d_in[2];
    const float* Wc = (const float*)d_in[3];
    const float* bc = (const float*)d_in[4];
    float* out = (float*)d_out;

    cudaFuncSetAttribute(mlssa_main,
                         cudaFuncAttributeMaxDynamicSharedMemorySize, SMEM_TOTAL);

    wsplit_kernel<<<512, 256>>>(W1);
    mlssa_main<<<NTOT / TM, 256, SMEM_TOTAL>>>(x, W2, Wc, bc, out);
}

// round 7
// speedup vs baseline: 2.4757x; 1.1643x over previous
#include <cuda_runtime.h>
#include <cuda_fp16.h>
#include <mma.h>
#include <math.h>
#include <cstdint>

using namespace nvcuda;

#define NTOT   131072
#define DIM    512
#define DATT   256
#define NHEAD  4
#define NCLS   53
#define BAGSZ  16
#define NBAGS  8192

#define TM     64            // rows per block (4 bags); grid 2048
#define KC     32            // K chunk
#define NCHUNK (DIM / KC)    // 16
#define NSTAGE 3
#define A_LD   40            // fp16/row (32 + 8 pad) -> 80 B rows
#define B_LD   264           // fp16/row (256 + 8 pad) -> 528 B rows
#define H_LD   260

// stage layout (bytes): A 64*80=5120 | B 32*528=16896
#define STAGE_SZ 22016
#define A_OFF    0
#define B_OFF    5120
#define PIPE_SZ  (NSTAGE * STAGE_SZ)      // 66048

// hbuf overlays the pipeline after GEMM (66560 B); wcs/repr overlay hbuf later
#define HBUF_SZ  66560
#define OFF_WC   0                        // 16384, inside dead hbuf
#define OFF_REPR 16384                    // 8192, inside dead hbuf
#define OFF_W2   HBUF_SZ                  // 4096
#define OFF_SS   (OFF_W2 + 4096)          // 1024
#define OFF_WR   (OFF_SS + 1024)          // 256
#define SMEM_TOTAL (OFF_WR + 256)         // 71936 (~70.25 KB)

// pre-converted W1 (fp16), k-major: [k(512)][n(256)]
__device__ __align__(16) __half g_Wpk[DIM * DATT];

extern __shared__ char smem_raw[];

__device__ __forceinline__ uint32_t smem_u32(const void* p) {
    uint32_t a;
    asm("{ .reg .u64 t; cvta.to.shared.u64 t, %1; cvt.u32.u64 %0, t; }" : "=r"(a) : "l"(p));
    return a;
}
__device__ __forceinline__ void cp16(uint32_t dst, const void* src) {
    asm volatile("cp.async.ca.shared.global [%0], [%1], 16;" :: "r"(dst), "l"(src));
}
#define CP_COMMIT() asm volatile("cp.async.commit_group;" ::: "memory")
#define CP_WAIT1()  asm volatile("cp.async.wait_group 1;" ::: "memory")
#define CP_WAIT0()  asm volatile("cp.async.wait_group 0;" ::: "memory")

// overflow-safe fast tanh: rel err ~1e-6 via __expf of negative arg
__device__ __forceinline__ float fast_tanh(float v) {
    const float a = fabsf(v);
    const float e = __expf(-2.0f * a);
    const float t = (1.0f - e) * __frcp_rn(1.0f + e);
    return copysignf(t, v);
}

// one-time: W1 (512x256 f32) -> fp16
__global__ void wsplit_kernel(const float* __restrict__ W1) {
    const int idx = blockIdx.x * 256 + threadIdx.x;
    g_Wpk[idx] = __float2half(W1[idx]);
}

__device__ __forceinline__ void issue_b(int c, uint32_t sbase, int tid) {
    const uint32_t dst0 = sbase + (c % NSTAGE) * STAGE_SZ + B_OFF;
    const __half* src0 = g_Wpk + (size_t)c * (KC * DATT);
    #pragma unroll
    for (int it = 0; it < 4; it++) {
        const int q = it * 256 + tid;                  // 1024 x 16B
        const int row = q >> 5, seg = q & 31;
        cp16(dst0 + row * (B_LD * 2) + seg * 16, src0 + row * DATT + seg * 8);
    }
    CP_COMMIT();
}

// A chunk: each thread owns 8 consecutive floats of one row
__device__ __forceinline__ void ld_a(const float* __restrict__ x, int row0,
                                     int c, int tid, float4& v0, float4& v1) {
    const int row = tid >> 2, cg = tid & 3;
    const float* src = x + (size_t)(row0 + row) * DIM + c * KC + cg * 8;
    v0 = *(const float4*)src;
    v1 = *(const float4*)(src + 4);
}
__device__ __forceinline__ void st_a(int c, uint32_t sbase, int tid,
                                     float4 v0, float4 v1) {
    const int row = tid >> 2, cg = tid & 3;
    const uint32_t base = sbase + (c % NSTAGE) * STAGE_SZ + A_OFF + row * 80 + cg * 16;
    __half h0 = __float2half(v0.x), h1 = __float2half(v0.y);
    __half h2 = __float2half(v0.z), h3 = __float2half(v0.w);
    __half h4 = __float2half(v1.x), h5 = __float2half(v1.y);
    __half h6 = __float2half(v1.z), h7 = __float2half(v1.w);
    uint4 hv = make_uint4(
        (uint32_t)__half_as_ushort(h0) | ((uint32_t)__half_as_ushort(h1) << 16),
        (uint32_t)__half_as_ushort(h2) | ((uint32_t)__half_as_ushort(h3) << 16),
        (uint32_t)__half_as_ushort(h4) | ((uint32_t)__half_as_ushort(h5) << 16),
        (uint32_t)__half_as_ushort(h6) | ((uint32_t)__half_as_ushort(h7) << 16));
    asm volatile("st.shared.v4.b32 [%0], {%1,%2,%3,%4};" ::
        "r"(base), "r"(hv.x), "r"(hv.y), "r"(hv.z), "r"(hv.w));
}

__global__ __launch_bounds__(256, 2)
void mlssa_main(const float* __restrict__ x, const float* __restrict__ W2,
                const float* __restrict__ Wc, const float* __restrict__ bc,
                float* __restrict__ out)
{
    const int tid  = threadIdx.x;
    const int wid  = tid >> 5;
    const int row0 = blockIdx.x * TM;
    const uint32_t sbase = smem_u32(smem_raw);

    float* hbuf = (float*)(smem_raw);               // overlays pipeline post-GEMM
    float* wcs  = (float*)(smem_raw + OFF_WC);      // overlays hbuf post-scores
    float* repr = (float*)(smem_raw + OFF_REPR);    // overlays hbuf post-scores
    float* w2s  = (float*)(smem_raw + OFF_W2);
    float* ss   = (float*)(smem_raw + OFF_SS);
    float* wr   = (float*)(smem_raw + OFF_WR);

    // prologue: chunks 0,1 staged; prefetch chunk 2 into regs
    issue_b(0, sbase, tid);
    issue_b(1, sbase, tid);
    {
        float4 a0, a1;
        ld_a(x, row0, 0, tid, a0, a1); st_a(0, sbase, tid, a0, a1);
        ld_a(x, row0, 1, tid, a0, a1); st_a(1, sbase, tid, a0, a1);
    }
    float4 rA0, rA1;
    ld_a(x, row0, 2, tid, rA0, rA1);

    for (int i = tid; i < DATT * NHEAD; i += 256) w2s[i] = W2[i];
    ss[tid] = 0.0f;

    const int warp_m = wid >> 2;   // 2(M) x 4(N), warp tile 32x64
    const int warp_n = wid & 3;

    wmma::fragment<wmma::accumulator, 16, 16, 16, float> acc[2][4];
    #pragma unroll
    for (int i = 0; i < 2; i++)
        #pragma unroll
        for (int j = 0; j < 4; j++) wmma::fill_fragment(acc[i][j], 0.0f);

    for (int c = 0; c < NCHUNK; c++) {
        if (c == NCHUNK - 1) { CP_WAIT0(); } else { CP_WAIT1(); }
        __syncthreads();   // chunk c visible; stage (c+2)%3 dead

        if (c + 2 < NCHUNK) {
            st_a(c + 2, sbase, tid, rA0, rA1);
            issue_b(c + 2, sbase, tid);
            if (c + 3 < NCHUNK) ld_a(x, row0, c + 3, tid, rA0, rA1);
        }

        const char* stg = smem_raw + (c % NSTAGE) * STAGE_SZ;
        const __half* Ap = (const __half*)(stg + A_OFF);
        const __half* Bp = (const __half*)(stg + B_OFF);

        #pragma unroll
        for (int ks = 0; ks < 2; ks++) {
            wmma::fragment<wmma::matrix_a, 16, 16, 16, __half, wmma::row_major> af[2];
            wmma::fragment<wmma::matrix_b, 16, 16, 16, __half, wmma::row_major> bf[4];
            #pragma unroll
            for (int i = 0; i < 2; i++)
                wmma::load_matrix_sync(af[i],
                    Ap + (size_t)(warp_m * 32 + i * 16) * A_LD + ks * 16, A_LD);
            #pragma unroll
            for (int j = 0; j < 4; j++)
                wmma::load_matrix_sync(bf[j],
                    Bp + (size_t)(ks * 16) * B_LD + warp_n * 64 + j * 16, B_LD);
            #pragma unroll
            for (int i = 0; i < 2; i++)
                #pragma unroll
                for (int j = 0; j < 4; j++)
                    wmma::mma_sync(acc[i][j], af[i], bf[j], acc[i][j]);
        }
    }

    __syncthreads();   // pipeline dead -> h overlay safe
    #pragma unroll
    for (int i = 0; i < 2; i++)
        #pragma unroll
        for (int j = 0; j < 4; j++)
            wmma::store_matrix_sync(
                hbuf + (size_t)(warp_m * 32 + i * 16) * H_LD + warp_n * 64 + j * 16,
                acc[i][j], H_LD, wmma::mem_row_major);
    __syncthreads();

    // scores: s[r][h] = sum_c tanh(h[r][c]) * W2[c][h]
    {
        const int r = tid & 63;
        const int q = tid >> 6;
        float sp0 = 0.f, sp1 = 0.f, sp2 = 0.f, sp3 = 0.f;
        const float* hr = hbuf + (size_t)r * H_LD + q * 64;
        #pragma unroll
        for (int jj = 0; jj < 16; jj++) {
            const float4 hv = *(const float4*)&hr[jj * 4];
            #pragma unroll
            for (int s = 0; s < 4; s++) {
                const float hvv = (s == 0) ? hv.x : (s == 1) ? hv.y : (s == 2) ? hv.z : hv.w;
                const float t = fast_tanh(hvv);
                const float4 wv = *(const float4*)&w2s[(q * 64 + jj * 4 + s) * 4];
                sp0 += t * wv.x; sp1 += t * wv.y; sp2 += t * wv.z; sp3 += t * wv.w;
            }
        }
        atomicAdd(&ss[r * 4 + 0], sp0);
        atomicAdd(&ss[r * 4 + 1], sp1);
        atomicAdd(&ss[r * 4 + 2], sp2);
        atomicAdd(&ss[r * 4 + 3], sp3);
    }
    __syncthreads();

    // per-bag softmax over 16 rows, mean over 4 heads
    if (tid < TM) {
        const int r = tid, b0 = r & ~15;
        float ws = 0.f;
        #pragma unroll
        for (int h = 0; h < NHEAD; h++) {
            float m = -1e30f;
            #pragma unroll
            for (int q = 0; q < BAGSZ; q++) m = fmaxf(m, ss[(b0 + q) * 4 + h]);
            float den = 0.f;
            #pragma unroll
            for (int q = 0; q < BAGSZ; q++) den += expf(ss[(b0 + q) * 4 + h] - m);
            ws += expf(ss[r * 4 + h] - m) / den;
        }
        wr[r] = ws * 0.25f;
    }
    __syncthreads();

    // pooling: thread owns 2 dims across 4 bags; exact fp32 x from global (L2-hot)
    {
        const int d0 = tid * 2;
        #pragma unroll
        for (int b = 0; b < TM / BAGSZ; b++) {
            float s0 = 0.f, s1 = 0.f;
            #pragma unroll 4
            for (int q = 0; q < BAGSZ; q++) {
                const int rr = b * BAGSZ + q;
                const float w = wr[rr];
                const float2 v = *(const float2*)(x + (size_t)(row0 + rr) * DIM + d0);
                s0 += w * v.x;
                s1 += w * v.y;
            }
            repr[b * DIM + d0]     = s0;
            repr[b * DIM + d0 + 1] = s1;
        }
    }
    __syncthreads();

    // fused classifier: logits[bag] = repr[bag] @ Wc + bc
    {
        const int bag = tid >> 6;
        const int cls = tid & 63;
        float acc0 = 0.f;
        for (int k0 = 0; k0 < DIM; k0 += 64) {
            __syncthreads();
            for (int i = tid; i < 64 * 64; i += 256) {
                const int kk = i >> 6, cc = i & 63;
                wcs[i] = (cc < NCLS) ? Wc[(size_t)(k0 + kk) * NCLS + cc] : 0.f;
            }
            __syncthreads();
            #pragma unroll 8
            for (int kk = 0; kk < 64; kk++)
                acc0 += repr[bag * DIM + k0 + kk] * wcs[kk * 64 + cls];
        }
        if (cls < NCLS) {
            const int bag_g = blockIdx.x * (TM / BAGSZ) + bag;
            out[(size_t)bag_g * NCLS + cls] = acc0 + bc[cls];
        }
    }
}

extern "C" void kernel_launch(void* const* d_in, const int* in_sizes, int n_in,
                              void* d_out, int out_size)
{
    const float* x  = (const float*)d_in[0];
    const float* W1 = (const float*)d_in[1];
    const float* W2 = (const float*)d_in[2];
    const float* Wc = (const float*)d_in[3];
    const float* bc = (const float*)d_in[4];
    float* out = (float*)d_out;

    cudaFuncSetAttribute(mlssa_main,
                         cudaFuncAttributeMaxDynamicSharedMemorySize, SMEM_TOTAL);

    wsplit_kernel<<<512, 256>>>(W1);
    mlssa_main<<<NTOT / TM, 256, SMEM_TOTAL>>>(x, W2, Wc, bc, out);
}

// round 8
// speedup vs baseline: 3.2406x; 1.3090x over previous
#include <cuda_runtime.h>
#include <cuda_fp16.h>
#include <mma.h>
#include <math.h>
#include <cstdint>

using namespace nvcuda;

#define NTOT   131072
#define DIM    512
#define DATT   256
#define NHEAD  4
#define NCLS   53
#define NCLP   64            // padded classes
#define BAGSZ  16
#define NBAGS  8192

#define TM     64            // rows per block (4 bags); grid 2048
#define KC     32            // K chunk
#define NCHUNK (DIM / KC)    // 16
#define NSTAGE 3
#define A_LD   40            // fp16/row (32 + 8 pad)
#define B_LD   264           // fp16/row (256 + 8 pad)
#define H_LD   260

// stage layout (bytes): A 64*80=5120 | B 32*528=16896
#define STAGE_SZ 22016
#define A_OFF    0
#define B_OFF    5120
#define PIPE_SZ  (NSTAGE * STAGE_SZ)      // 66048

// region 0..66560 is a union: pipeline -> hbuf(66560) -> Wc fp16 image (65536)
#define HBUF_SZ   66560
#define OFF_W2    HBUF_SZ                 // 4096
#define OFF_SS    (OFF_W2 + 4096)         // 1024
#define OFF_WR    (OFF_SS + 1024)         // 256
#define OFF_REPR  (OFF_WR + 256)          // 8192 (4 bags x 512 f32)
#define OFF_PART  (OFF_REPR + 8192)       // 8192 (8 segs x 4 bags x 64 cls f32)
#define SMEM_TOTAL (OFF_PART + 8192)      // 88320

// pre-converted weights (device globals)
__device__ __align__(16) __half g_Wpk[DIM * DATT];     // W1 fp16, k-major
__device__ __align__(16) __half g_Wc16[DIM * NCLP];    // Wc fp16, [k][64] padded

extern __shared__ char smem_raw[];

__device__ __forceinline__ uint32_t smem_u32(const void* p) {
    uint32_t a;
    asm("{ .reg .u64 t; cvta.to.shared.u64 t, %1; cvt.u32.u64 %0, t; }" : "=r"(a) : "l"(p));
    return a;
}
__device__ __forceinline__ void cp16(uint32_t dst, const void* src) {
    asm volatile("cp.async.ca.shared.global [%0], [%1], 16;" :: "r"(dst), "l"(src));
}
#define CP_COMMIT() asm volatile("cp.async.commit_group;" ::: "memory")
#define CP_WAIT1()  asm volatile("cp.async.wait_group 1;" ::: "memory")
#define CP_WAIT0()  asm volatile("cp.async.wait_group 0;" ::: "memory")

__device__ __forceinline__ float fast_tanh(float v) {
    const float a = fabsf(v);
    const float e = __expf(-2.0f * a);
    const float t = (1.0f - e) * __frcp_rn(1.0f + e);
    return copysignf(t, v);
}

// one-time: W1 -> fp16
__global__ void wsplit_kernel(const float* __restrict__ W1) {
    const int idx = blockIdx.x * 256 + threadIdx.x;
    g_Wpk[idx] = __float2half(W1[idx]);
}
// one-time: Wc -> fp16 padded [512][64]
__global__ void wcprep_kernel(const float* __restrict__ Wc) {
    const int idx = blockIdx.x * 256 + threadIdx.x;   // k*64 + c
    const int k = idx >> 6, c = idx & 63;
    g_Wc16[idx] = (c < NCLS) ? __float2half(Wc[k * NCLS + c]) : __float2half(0.f);
}

__device__ __forceinline__ void issue_b(int c, uint32_t sbase, int tid) {
    const uint32_t dst0 = sbase + (c % NSTAGE) * STAGE_SZ + B_OFF;
    const __half* src0 = g_Wpk + (size_t)c * (KC * DATT);
    #pragma unroll
    for (int it = 0; it < 4; it++) {
        const int q = it * 256 + tid;
        const int row = q >> 5, seg = q & 31;
        cp16(dst0 + row * (B_LD * 2) + seg * 16, src0 + row * DATT + seg * 8);
    }
    CP_COMMIT();
}

__device__ __forceinline__ void ld_a(const float* __restrict__ x, int row0,
                                     int c, int tid, float4& v0, float4& v1) {
    const int row = tid >> 2, cg = tid & 3;
    const float* src = x + (size_t)(row0 + row) * DIM + c * KC + cg * 8;
    v0 = *(const float4*)src;
    v1 = *(const float4*)(src + 4);
}
__device__ __forceinline__ void st_a(int c, uint32_t sbase, int tid,
                                     float4 v0, float4 v1) {
    const int row = tid >> 2, cg = tid & 3;
    const uint32_t base = sbase + (c % NSTAGE) * STAGE_SZ + A_OFF + row * 80 + cg * 16;
    __half h0 = __float2half(v0.x), h1 = __float2half(v0.y);
    __half h2 = __float2half(v0.z), h3 = __float2half(v0.w);
    __half h4 = __float2half(v1.x), h5 = __float2half(v1.y);
    __half h6 = __float2half(v1.z), h7 = __float2half(v1.w);
    uint4 hv = make_uint4(
        (uint32_t)__half_as_ushort(h0) | ((uint32_t)__half_as_ushort(h1) << 16),
        (uint32_t)__half_as_ushort(h2) | ((uint32_t)__half_as_ushort(h3) << 16),
        (uint32_t)__half_as_ushort(h4) | ((uint32_t)__half_as_ushort(h5) << 16),
        (uint32_t)__half_as_ushort(h6) | ((uint32_t)__half_as_ushort(h7) << 16));
    asm volatile("st.shared.v4.b32 [%0], {%1,%2,%3,%4};" ::
        "r"(base), "r"(hv.x), "r"(hv.y), "r"(hv.z), "r"(hv.w));
}

__global__ __launch_bounds__(256, 2)
void mlssa_main(const float* __restrict__ x, const float* __restrict__ W2,
                const float* __restrict__ bc, float* __restrict__ out)
{
    const int tid  = threadIdx.x;
    const int wid  = tid >> 5;
    const int row0 = blockIdx.x * TM;
    const uint32_t sbase = smem_u32(smem_raw);

    float*  hbuf = (float*)(smem_raw);            // overlays pipeline post-GEMM
    __half* wch  = (__half*)(smem_raw);           // overlays hbuf post-scores
    float*  w2s  = (float*)(smem_raw + OFF_W2);
    float*  ss   = (float*)(smem_raw + OFF_SS);
    float*  wr   = (float*)(smem_raw + OFF_WR);
    float*  repr = (float*)(smem_raw + OFF_REPR);
    float*  part = (float*)(smem_raw + OFF_PART);

    // prologue
    issue_b(0, sbase, tid);
    issue_b(1, sbase, tid);
    {
        float4 a0, a1;
        ld_a(x, row0, 0, tid, a0, a1); st_a(0, sbase, tid, a0, a1);
        ld_a(x, row0, 1, tid, a0, a1); st_a(1, sbase, tid, a0, a1);
    }
    float4 rA0, rA1;
    ld_a(x, row0, 2, tid, rA0, rA1);

    for (int i = tid; i < DATT * NHEAD; i += 256) w2s[i] = W2[i];
    ss[tid] = 0.0f;

    const int warp_m = wid >> 2;
    const int warp_n = wid & 3;

    wmma::fragment<wmma::accumulator, 16, 16, 16, float> acc[2][4];
    #pragma unroll
    for (int i = 0; i < 2; i++)
        #pragma unroll
        for (int j = 0; j < 4; j++) wmma::fill_fragment(acc[i][j], 0.0f);

    for (int c = 0; c < NCHUNK; c++) {
        if (c == NCHUNK - 1) { CP_WAIT0(); } else { CP_WAIT1(); }
        __syncthreads();

        if (c + 2 < NCHUNK) {
            st_a(c + 2, sbase, tid, rA0, rA1);
            issue_b(c + 2, sbase, tid);
            if (c + 3 < NCHUNK) ld_a(x, row0, c + 3, tid, rA0, rA1);
        }

        const char* stg = smem_raw + (c % NSTAGE) * STAGE_SZ;
        const __half* Ap = (const __half*)(stg + A_OFF);
        const __half* Bp = (const __half*)(stg + B_OFF);

        #pragma unroll
        for (int ks = 0; ks < 2; ks++) {
            wmma::fragment<wmma::matrix_a, 16, 16, 16, __half, wmma::row_major> af[2];
            wmma::fragment<wmma::matrix_b, 16, 16, 16, __half, wmma::row_major> bf[4];
            #pragma unroll
            for (int i = 0; i < 2; i++)
                wmma::load_matrix_sync(af[i],
                    Ap + (size_t)(warp_m * 32 + i * 16) * A_LD + ks * 16, A_LD);
            #pragma unroll
            for (int j = 0; j < 4; j++)
                wmma::load_matrix_sync(bf[j],
                    Bp + (size_t)(ks * 16) * B_LD + warp_n * 64 + j * 16, B_LD);
            #pragma unroll
            for (int i = 0; i < 2; i++)
                #pragma unroll
                for (int j = 0; j < 4; j++)
                    wmma::mma_sync(acc[i][j], af[i], bf[j], acc[i][j]);
        }
    }

    __syncthreads();
    #pragma unroll
    for (int i = 0; i < 2; i++)
        #pragma unroll
        for (int j = 0; j < 4; j++)
            wmma::store_matrix_sync(
                hbuf + (size_t)(warp_m * 32 + i * 16) * H_LD + warp_n * 64 + j * 16,
                acc[i][j], H_LD, wmma::mem_row_major);
    __syncthreads();

    // scores: s[r][h] = sum_c tanh(h[r][c]) * W2[c][h]
    {
        const int r = tid & 63;
        const int q = tid >> 6;
        float sp0 = 0.f, sp1 = 0.f, sp2 = 0.f, sp3 = 0.f;
        const float* hr = hbuf + (size_t)r * H_LD + q * 64;
        #pragma unroll
        for (int jj = 0; jj < 16; jj++) {
            const float4 hv = *(const float4*)&hr[jj * 4];
            #pragma unroll
            for (int s = 0; s < 4; s++) {
                const float hvv = (s == 0) ? hv.x : (s == 1) ? hv.y : (s == 2) ? hv.z : hv.w;
                const float t = fast_tanh(hvv);
                const float4 wv = *(const float4*)&w2s[(q * 64 + jj * 4 + s) * 4];
                sp0 += t * wv.x; sp1 += t * wv.y; sp2 += t * wv.z; sp3 += t * wv.w;
            }
        }
        atomicAdd(&ss[r * 4 + 0], sp0);
        atomicAdd(&ss[r * 4 + 1], sp1);
        atomicAdd(&ss[r * 4 + 2], sp2);
        atomicAdd(&ss[r * 4 + 3], sp3);
    }
    __syncthreads();   // hbuf dead past here

    // kick Wc fp16 image into smem (overlaps softmax + pooling)
    {
        #pragma unroll
        for (int it = 0; it < 16; it++) {
            const int q = it * 256 + tid;              // 4096 x 16B
            const int row = q >> 3, seg = q & 7;
            cp16(sbase + row * 128 + seg * 16, g_Wc16 + (size_t)row * NCLP + seg * 8);
        }
        CP_COMMIT();
    }

    // per-bag softmax over 16 rows, mean over 4 heads
    if (tid < TM) {
        const int r = tid, b0 = r & ~15;
        float ws = 0.f;
        #pragma unroll
        for (int h = 0; h < NHEAD; h++) {
            float m = -1e30f;
            #pragma unroll
            for (int q = 0; q < BAGSZ; q++) m = fmaxf(m, ss[(b0 + q) * 4 + h]);
            float den = 0.f;
            #pragma unroll
            for (int q = 0; q < BAGSZ; q++) den += expf(ss[(b0 + q) * 4 + h] - m);
            ws += expf(ss[r * 4 + h] - m) / den;
        }
        wr[r] = ws * 0.25f;
    }
    __syncthreads();

    // pooling: thread owns (bag, 8-dim block); vectorized, high MLP
    {
        const int bag = tid >> 6;
        const int d0  = (tid & 63) * 8;
        float a0 = 0.f, a1 = 0.f, a2 = 0.f, a3 = 0.f;
        float a4 = 0.f, a5 = 0.f, a6 = 0.f, a7 = 0.f;
        #pragma unroll 4
        for (int q = 0; q < BAGSZ; q++) {
            const int rr = bag * BAGSZ + q;
            const float w = wr[rr];
            const float* src = x + (size_t)(row0 + rr) * DIM + d0;
            const float4 v0 = *(const float4*)src;
            const float4 v1 = *(const float4*)(src + 4);
            a0 += w * v0.x; a1 += w * v0.y; a2 += w * v0.z; a3 += w * v0.w;
            a4 += w * v1.x; a5 += w * v1.y; a6 += w * v1.z; a7 += w * v1.w;
        }
        *(float4*)&repr[bag * DIM + d0]     = make_float4(a0, a1, a2, a3);
        *(float4*)&repr[bag * DIM + d0 + 4] = make_float4(a4, a5, a6, a7);
    }
    CP_WAIT0();
    __syncthreads();   // repr + wch ready

    // classifier: thread owns 2 classes x 64-k segment x 4 bags
    {
        const int cls2 = (tid & 31) * 2;
        const int seg  = tid >> 5;            // 0..7
        float b0a = 0.f, b0b = 0.f, b1a = 0.f, b1b = 0.f;
        float b2a = 0.f, b2b = 0.f, b3a = 0.f, b3b = 0.f;
        const int k0 = seg * 64;
        #pragma unroll 8
        for (int k = 0; k < 64; k++) {
            const __half2 wv = *(const __half2*)&wch[(k0 + k) * NCLP + cls2];
            const float wa = __half2float(__low2half(wv));
            const float wb = __half2float(__high2half(wv));
            const float r0 = repr[0 * DIM + k0 + k];
            const float r1 = repr[1 * DIM + k0 + k];
            const float r2 = repr[2 * DIM + k0 + k];
            const float r3 = repr[3 * DIM + k0 + k];
            b0a += r0 * wa; b0b += r0 * wb;
            b1a += r1 * wa; b1b += r1 * wb;
            b2a += r2 * wa; b2b += r2 * wb;
            b3a += r3 * wa; b3b += r3 * wb;
        }
        float* p = part + seg * 256;          // [bag][cls]
        p[0 * 64 + cls2] = b0a; p[0 * 64 + cls2 + 1] = b0b;
        p[1 * 64 + cls2] = b1a; p[1 * 64 + cls2 + 1] = b1b;
        p[2 * 64 + cls2] = b2a; p[2 * 64 + cls2 + 1] = b2b;
        p[3 * 64 + cls2] = b3a; p[3 * 64 + cls2 + 1] = b3b;
    }
    __syncthreads();

    // reduce 8 segments, add bias, store
    {
        const int bag = tid >> 6;
        const int cls = tid & 63;
        if (cls < NCLS) {
            float s = 0.f;
            #pragma unroll
            for (int g = 0; g < 8; g++) s += part[g * 256 + bag * 64 + cls];
            const int bag_g = blockIdx.x * (TM / BAGSZ) + bag;
            out[(size_t)bag_g * NCLS + cls] = s + bc[cls];
        }
    }
}

extern "C" void kernel_launch(void* const* d_in, const int* in_sizes, int n_in,
                              void* d_out, int out_size)
{
    const float* x  = (const float*)d_in[0];
    const float* W1 = (const float*)d_in[1];
    const float* W2 = (const float*)d_in[2];
    const float* Wc = (const float*)d_in[3];
    const float* bc = (const float*)d_in[4];
    float* out = (float*)d_out;

    cudaFuncSetAttribute(mlssa_main,
                         cudaFuncAttributeMaxDynamicSharedMemorySize, SMEM_TOTAL);

    wsplit_kernel<<<512, 256>>>(W1);
    wcprep_kernel<<<(DIM * NCLP) / 256, 256>>>(Wc);
    mlssa_main<<<NTOT / TM, 256, SMEM_TOTAL>>>(x, W2, bc, out);
}